// round 16
// baseline (speedup 1.0000x reference)
#include <cuda_runtime.h>
#include <cuda_fp16.h>
#include <cstdint>

// B=8, N=512, T=64, D=128, H=8, DK=16, K=3.
// R16: M=64/CTA, 256 thr = 8 warps, warp tile 32x32, target 3 CTA/SM (<=84 regs).
// fp16 MMA, fp32 accum. 8KB quarter-chunk cp.async pipeline.
// k-tile overwrites dead key input in S_IN; x overwrites dead q tile in QP.

// byte offsets in dynamic smem (per CTA 70208 B)
#define S_IN_B   0          // 68 rows x 272B fp16: value -> query -> key -> k-tile(rows+2)
#define S_ST_B   18496      // 2 x 8KB double-buffered weight quarter-chunk
#define S_QP_B   34880      // 64 x 272B fp16 q tile -> x tile
#define S_VT_B   52288      // 64 x 272B fp16 v tile
#define S_MSK_B  69696      // 64 x ull row masks
#define SMEM_BYTES 70208

// g_pack offsets (uint32 units). 32KB chunk = 8192 u32; quarter = 2048 u32.
#define PQ4 0
#define PK4 24576
#define PV4 49152
#define PO4 57344

typedef unsigned long long ull;
__device__ uint32_t g_pack[65536];

// ---------------- PTX helpers ----------------
__device__ __forceinline__ uint32_t smem_u32(const void* p) {
    uint32_t a;
    asm("{ .reg .u64 t; cvta.to.shared.u64 t, %1; cvt.u32.u64 %0, t; }" : "=r"(a) : "l"(p));
    return a;
}
__device__ __forceinline__ uint32_t h2(float lo, float hi) {
    uint32_t r; asm("cvt.rn.f16x2.f32 %0, %1, %2;" : "=r"(r) : "f"(hi), "f"(lo)); return r;
}
__device__ __forceinline__ uint4 lds128(uint32_t a) {
    uint4 v;
    asm volatile("ld.shared.v4.b32 {%0,%1,%2,%3}, [%4];"
                 : "=r"(v.x), "=r"(v.y), "=r"(v.z), "=r"(v.w) : "r"(a));
    return v;
}
__device__ __forceinline__ void ldsm4(uint32_t (&r)[4], uint32_t a) {
    asm volatile("ldmatrix.sync.aligned.m8n8.x4.shared.b16 {%0,%1,%2,%3}, [%4];"
                 : "=r"(r[0]), "=r"(r[1]), "=r"(r[2]), "=r"(r[3]) : "r"(a));
}
__device__ __forceinline__ void ldsm4t(uint32_t (&r)[4], uint32_t a) {
    asm volatile("ldmatrix.sync.aligned.m8n8.x4.trans.shared.b16 {%0,%1,%2,%3}, [%4];"
                 : "=r"(r[0]), "=r"(r[1]), "=r"(r[2]), "=r"(r[3]) : "r"(a));
}
__device__ __forceinline__ void mma16(float (&c)[4], const uint32_t (&a)[4],
                                      uint32_t b0, uint32_t b1) {
    asm volatile(
        "mma.sync.aligned.m16n8k16.row.col.f32.f16.f16.f32 "
        "{%0,%1,%2,%3},{%4,%5,%6,%7},{%8,%9},{%0,%1,%2,%3};"
        : "+f"(c[0]), "+f"(c[1]), "+f"(c[2]), "+f"(c[3])
        : "r"(a[0]), "r"(a[1]), "r"(a[2]), "r"(a[3]), "r"(b0), "r"(b1));
}
// register-free global->shared prefetch of one 8KB quarter (256 thr: 2 ops)
__device__ __forceinline__ void cpasyncQ(uint32_t smb, int buf, const uint32_t* __restrict__ g,
                                         int tid) {
    const uint4* g4 = (const uint4*)g;
#pragma unroll
    for (int r = 0; r < 2; r++) {
        uint32_t dst = smb + S_ST_B + (uint32_t)(buf * 8192 + (tid + r * 256) * 16);
        asm volatile("cp.async.cg.shared.global [%0], [%1], 16;"
                     :: "r"(dst), "l"(g4 + tid + r * 256) : "memory");
    }
    asm volatile("cp.async.commit_group;" ::: "memory");
}
#define CP_WAIT0() asm volatile("cp.async.wait_group 0;" ::: "memory")

// ---------------- prep: pack weights as fp16 B-fragments (unchanged) ------------
__global__ void prep_kernel(const float* __restrict__ Wq, const float* __restrict__ Wk,
                            const float* __restrict__ Wv, const float* __restrict__ Wo) {
    int idx = blockIdx.x * blockDim.x + threadIdx.x;   // 16384
    if (idx >= 16384) return;
    const float* W; int base4, within, j = 0, conv; float sc = 1.0f;
    if (idx < 6144)       { W = Wq; j = idx >> 11; within = idx & 2047; base4 = PQ4 / 4 + idx; conv = 1; sc = 0.25f; }
    else if (idx < 12288) { int i2 = idx - 6144; W = Wk; j = i2 >> 11; within = i2 & 2047; base4 = PK4 / 4 + i2; conv = 1; }
    else if (idx < 14336) { int i2 = idx - 12288; W = Wv; within = i2; base4 = PV4 / 4 + i2; conv = 0; }
    else                  { int i2 = idx - 14336; W = Wo; within = i2; base4 = PO4 / 4 + i2; conv = 0; }
    int lane = within & 31, njp = (within >> 5) & 7, ksp = within >> 8;
    int n0 = njp * 16 + (lane >> 2);
    int n1 = n0 + 8;
    int k0 = ksp * 16 + 2 * (lane & 3);
    float w[8];
    if (conv) {
        w[0] = W[(n0 * 128 + k0) * 3 + j];     w[1] = W[(n0 * 128 + k0 + 1) * 3 + j];
        w[2] = W[(n0 * 128 + k0 + 8) * 3 + j]; w[3] = W[(n0 * 128 + k0 + 9) * 3 + j];
        w[4] = W[(n1 * 128 + k0) * 3 + j];     w[5] = W[(n1 * 128 + k0 + 1) * 3 + j];
        w[6] = W[(n1 * 128 + k0 + 8) * 3 + j]; w[7] = W[(n1 * 128 + k0 + 9) * 3 + j];
    } else {
        w[0] = W[n0 * 128 + k0];     w[1] = W[n0 * 128 + k0 + 1];
        w[2] = W[n0 * 128 + k0 + 8]; w[3] = W[n0 * 128 + k0 + 9];
        w[4] = W[n1 * 128 + k0];     w[5] = W[n1 * 128 + k0 + 1];
        w[6] = W[n1 * 128 + k0 + 8]; w[7] = W[n1 * 128 + k0 + 9];
    }
    uint4 o;
    o.x = h2(w[0] * sc, w[1] * sc);
    o.y = h2(w[2] * sc, w[3] * sc);
    o.z = h2(w[4] * sc, w[5] * sc);
    o.w = h2(w[6] * sc, w[7] * sc);
    ((uint4*)g_pack)[base4] = o;
}

// ---------------- building blocks ----------------
__device__ __forceinline__ void load_input(char* smc, const float* __restrict__ g, int tid) {
#pragma unroll
    for (int r = 0; r < 8; r++) {
        int idx = tid + r * 256;
        float4 f = *(const float4*)(g + idx * 4);
        int t = idx >> 5, d = (idx & 31) * 4;
        uint2 v;
        v.x = h2(f.x, f.y);
        v.y = h2(f.z, f.w);
        *(uint2*)(smc + S_IN_B + (t + 2) * 272 + d * 2) = v;
    }
}
// one 8KB quarter: 2 k16-steps, warp tile 32x32
__device__ __forceinline__ void mma_quarter(float (&acc)[2][4][4], uint32_t a0, uint32_t b0) {
#pragma unroll
    for (int ksp = 0; ksp < 2; ksp++) {
        uint32_t A0[4], A1[4];
        ldsm4(A0, a0 + ksp * 32);
        ldsm4(A1, a0 + 16 * 272 + ksp * 32);
        uint4 B01 = lds128(b0 + ksp * 4096);
        uint4 B23 = lds128(b0 + ksp * 4096 + 512);
        mma16(acc[0][0], A0, B01.x, B01.y);
        mma16(acc[0][1], A0, B01.z, B01.w);
        mma16(acc[0][2], A0, B23.x, B23.y);
        mma16(acc[0][3], A0, B23.z, B23.w);
        mma16(acc[1][0], A1, B01.x, B01.y);
        mma16(acc[1][1], A1, B01.z, B01.w);
        mma16(acc[1][2], A1, B23.x, B23.y);
        mma16(acc[1][3], A1, B23.z, B23.w);
    }
}
__device__ __forceinline__ void zacc(float (&acc)[2][4][4]) {
#pragma unroll
    for (int s = 0; s < 2; s++)
#pragma unroll
        for (int i = 0; i < 4; i++)
#pragma unroll
            for (int k = 0; k < 4; k++) acc[s][i][k] = 0.f;
}
__device__ __forceinline__ void epi_s(char* smc, int baseoff, const float* __restrict__ bias,
                                      float bscale, float (&acc)[2][4][4],
                                      int lane, int mg, int ng) {
#pragma unroll
    for (int msub = 0; msub < 2; msub++) {
        int r0 = mg * 32 + msub * 16 + (lane >> 2);
#pragma unroll
        for (int nt = 0; nt < 4; nt++) {
            int col = ng * 32 + nt * 8 + (lane & 3) * 2;
            float2 bb = *(const float2*)(bias + col);
            *(uint32_t*)(smc + baseoff + r0 * 272 + col * 2) =
                h2(acc[msub][nt][0] + bb.x * bscale, acc[msub][nt][1] + bb.y * bscale);
            *(uint32_t*)(smc + baseoff + (r0 + 8) * 272 + col * 2) =
                h2(acc[msub][nt][2] + bb.x * bscale, acc[msub][nt][3] + bb.y * bscale);
        }
    }
}
__device__ __forceinline__ void epi_g(float* __restrict__ dst, const float* __restrict__ bias,
                                      float (&acc)[2][4][4], int lane, int mg, int ng) {
#pragma unroll
    for (int msub = 0; msub < 2; msub++) {
        int r0 = mg * 32 + msub * 16 + (lane >> 2);
#pragma unroll
        for (int nt = 0; nt < 4; nt++) {
            int col = ng * 32 + nt * 8 + (lane & 3) * 2;
            float2 bb = *(const float2*)(bias + col);
            *(float2*)(dst + r0 * 128 + col) = make_float2(acc[msub][nt][0] + bb.x, acc[msub][nt][1] + bb.y);
            *(float2*)(dst + (r0 + 8) * 128 + col) = make_float2(acc[msub][nt][2] + bb.x, acc[msub][nt][3] + bb.y);
        }
    }
}

__global__ void __launch_bounds__(256, 3)
attn_kernel(const float* __restrict__ query, const float* __restrict__ key,
            const float* __restrict__ value, const int* __restrict__ mask,
            const float* __restrict__ bq, const float* __restrict__ bk,
            const float* __restrict__ bv, const float* __restrict__ bo,
            float* __restrict__ out)
{
    extern __shared__ char smc[];
    uint32_t smb = smem_u32(smc);
    const int tid = threadIdx.x, lane = tid & 31, wid = tid >> 5;
    const int cta = blockIdx.x, b = cta >> 9;
    const long long base = (long long)cta * 8192;

    const int mg = wid >> 2, ng = wid & 3;
    const int rowbase = mg * 32 + (lane & 15);
    const uint32_t a_in = smb + S_IN_B + (uint32_t)(rowbase * 272 + (lane >> 4) * 16);
    const uint32_t a_qp = smb + S_QP_B + (uint32_t)(rowbase * 272 + (lane >> 4) * 16);
    const uint32_t b_lane = (uint32_t)((ng * 64 + lane) * 16);

    // ---- prologue ----
    cpasyncQ(smb, 0, g_pack + PV4, tid);
    if (tid < 136) {
        int rr = tid / 34, off = tid - rr * 34;
        int row = (rr < 2) ? rr : (64 + rr);
        *(ull*)(smc + S_IN_B + row * 272 + off * 8) = 0ull;
    }
    if (tid < 64) {
        ull m = 0;
        const int4* mr = (const int4*)(mask + b * 4096 + tid * 64);
#pragma unroll
        for (int u = 0; u < 16; u++) {
            int4 mm = mr[u];
            ull bits = (ull)(mm.x != 0) | ((ull)(mm.y != 0) << 1) |
                       ((ull)(mm.z != 0) << 2) | ((ull)(mm.w != 0) << 3);
            m |= bits << (u * 4);
        }
        *(ull*)(smc + S_MSK_B + tid * 8) = m;
    }
    load_input(smc, value + base, tid);
    CP_WAIT0();
    __syncthreads();

    float acc[2][4][4];
    int buf = 0;

    // ---- V GEMM: 4 quarters (tap 2) ----
    zacc(acc);
#pragma unroll 1
    for (int q = 0; q < 4; q++) {
        const uint32_t* nxt = (q < 3) ? (g_pack + PV4 + (q + 1) * 2048) : (g_pack + PQ4);
        cpasyncQ(smb, buf ^ 1, nxt, tid);
        mma_quarter(acc, a_in + 2 * 272 + q * 64, smb + S_ST_B + buf * 8192 + b_lane);
        CP_WAIT0(); __syncthreads();
        buf ^= 1;
    }
    epi_s(smc, S_VT_B, bv, 1.0f, acc, lane, mg, ng);
    load_input(smc, query + base, tid);
    __syncthreads();

    // ---- Q GEMM: 12 quarters (taps 0,1,2) ----
    zacc(acc);
#pragma unroll 1
    for (int q = 0; q < 12; q++) {
        const uint32_t* nxt = (q < 11) ? (g_pack + PQ4 + (q + 1) * 2048) : (g_pack + PK4);
        cpasyncQ(smb, buf ^ 1, nxt, tid);
        mma_quarter(acc, a_in + (q >> 2) * 272 + (q & 3) * 64, smb + S_ST_B + buf * 8192 + b_lane);
        CP_WAIT0(); __syncthreads();
        buf ^= 1;
    }
    epi_s(smc, S_QP_B, bq, 0.25f, acc, lane, mg, ng);
    load_input(smc, key + base, tid);
    __syncthreads();

    // ---- K GEMM: 12 quarters (taps 1,2,3) ----
    zacc(acc);
#pragma unroll 1
    for (int q = 0; q < 12; q++) {
        const uint32_t* nxt = (q < 11) ? (g_pack + PK4 + (q + 1) * 2048) : (g_pack + PO4);
        cpasyncQ(smb, buf ^ 1, nxt, tid);
        mma_quarter(acc, a_in + ((q >> 2) + 1) * 272 + (q & 3) * 64, smb + S_ST_B + buf * 8192 + b_lane);
        CP_WAIT0(); __syncthreads();
        buf ^= 1;
    }
    // k-tile overwrites dead key input (all mma reads of key completed at last barrier)
    epi_s(smc, S_IN_B + 544, bk, 1.0f, acc, lane, mg, ng);
    cpasyncQ(smb, buf ^ 1, g_pack + PO4 + 2048, tid);   // O q1 (O q0 already in buf)
    __syncthreads();                                    // k/q/v tiles visible

    // ---- attention: warp = head wid; rh x mt serial (low regs); x -> QP rows ----
    {
        const int h = wid;
        const int r = lane >> 2, c = lane & 3;
        const uint32_t kt_thr = smb + S_IN_B + 544u
            + (uint32_t)((((lane >> 4) << 3) + (lane & 7)) * 272
                         + h * 32 + ((lane >> 3) & 1) * 16);
        const uint32_t vt_thr = smb + S_VT_B
            + (uint32_t)(((((lane >> 3) & 1) << 3) + (lane & 7)) * 272
                         + h * 32 + (lane >> 4) * 16);
#pragma unroll 1
        for (int rh = 0; rh < 2; rh++) {
            const int mh = rh * 32;
#pragma unroll 1
            for (int mt = 0; mt < 2; mt++) {
                float pa[8][4];
#pragma unroll
                for (int nt = 0; nt < 8; nt++)
#pragma unroll
                    for (int i = 0; i < 4; i++) pa[nt][i] = 0.f;

                uint32_t A[4];
                ldsm4(A, smb + S_QP_B
                         + (uint32_t)((mh + mt * 16 + (lane & 15)) * 272
                                      + h * 32 + (lane >> 4) * 16));
#pragma unroll
                for (int ntp = 0; ntp < 4; ntp++) {
                    uint32_t Bf[4];
                    ldsm4(Bf, kt_thr + (uint32_t)(ntp * 16 * 272));
                    mma16(pa[2 * ntp], A, Bf[0], Bf[1]);
                    mma16(pa[2 * ntp + 1], A, Bf[2], Bf[3]);
                }

                // masked softmax for rows rA = mh+mt*16+r, rB = rA+8
                ull mA = *(const ull*)(smc + S_MSK_B + (mh + mt * 16 + r) * 8);
                ull mB = *(const ull*)(smc + S_MSK_B + (mh + mt * 16 + r + 8) * 8);
                float mxA = -3.0e38f, mxB = -3.0e38f;
#pragma unroll
                for (int nt = 0; nt < 8; nt++) {
                    int c0 = nt * 8 + 2 * c, c1 = c0 + 1;
                    float v;
                    v = ((mA >> c0) & 1) ? pa[nt][0] : -1.0e9f; pa[nt][0] = v; mxA = fmaxf(mxA, v);
                    v = ((mA >> c1) & 1) ? pa[nt][1] : -1.0e9f; pa[nt][1] = v; mxA = fmaxf(mxA, v);
                    v = ((mB >> c0) & 1) ? pa[nt][2] : -1.0e9f; pa[nt][2] = v; mxB = fmaxf(mxB, v);
                    v = ((mB >> c1) & 1) ? pa[nt][3] : -1.0e9f; pa[nt][3] = v; mxB = fmaxf(mxB, v);
                }
                mxA = fmaxf(mxA, __shfl_xor_sync(0xffffffffu, mxA, 1));
                mxA = fmaxf(mxA, __shfl_xor_sync(0xffffffffu, mxA, 2));
                mxB = fmaxf(mxB, __shfl_xor_sync(0xffffffffu, mxB, 1));
                mxB = fmaxf(mxB, __shfl_xor_sync(0xffffffffu, mxB, 2));
                float sA = 0.f, sB = 0.f;
#pragma unroll
                for (int nt = 0; nt < 8; nt++) {
                    float e;
                    e = __expf(pa[nt][0] - mxA); pa[nt][0] = e; sA += e;
                    e = __expf(pa[nt][1] - mxA); pa[nt][1] = e; sA += e;
                    e = __expf(pa[nt][2] - mxB); pa[nt][2] = e; sB += e;
                    e = __expf(pa[nt][3] - mxB); pa[nt][3] = e; sB += e;
                }
                sA += __shfl_xor_sync(0xffffffffu, sA, 1);
                sA += __shfl_xor_sync(0xffffffffu, sA, 2);
                sB += __shfl_xor_sync(0xffffffffu, sB, 1);
                sB += __shfl_xor_sync(0xffffffffu, sB, 2);
                float iA = 1.0f / sA, iB = 1.0f / sB;

                // P @ V
                float xacc[2][4];
#pragma unroll
                for (int n2 = 0; n2 < 2; n2++)
#pragma unroll
                    for (int i = 0; i < 4; i++) xacc[n2][i] = 0.f;
#pragma unroll
                for (int kp = 0; kp < 4; kp++) {
                    uint32_t Vf[4];
                    ldsm4t(Vf, vt_thr + (uint32_t)(kp * 16 * 272));
                    uint32_t Ax[4];
                    Ax[0] = h2(pa[2 * kp][0], pa[2 * kp][1]);
                    Ax[1] = h2(pa[2 * kp][2], pa[2 * kp][3]);
                    Ax[2] = h2(pa[2 * kp + 1][0], pa[2 * kp + 1][1]);
                    Ax[3] = h2(pa[2 * kp + 1][2], pa[2 * kp + 1][3]);
                    mma16(xacc[0], Ax, Vf[0], Vf[1]);
                    mma16(xacc[1], Ax, Vf[2], Vf[3]);
                }

                // x (normalized, fp16) -> QP rows (warp-local cols; rows disjoint from
                // any A-frag rows this warp still needs)
                int rA = mh + mt * 16 + r, rB = rA + 8;
#pragma unroll
                for (int n2 = 0; n2 < 2; n2++) {
                    int col = h * 16 + n2 * 8 + 2 * c;
                    *(uint32_t*)(smc + S_QP_B + rA * 272 + col * 2) =
                        h2(xacc[n2][0] * iA, xacc[n2][1] * iA);
                    *(uint32_t*)(smc + S_QP_B + rB * 272 + col * 2) =
                        h2(xacc[n2][2] * iB, xacc[n2][3] * iB);
                }
            }
        }
    }
    CP_WAIT0();
    __syncthreads();                        // x tile + O q0,q1 visible

    // ---- O-projection: q0,q1 then q2,q3 ----
    zacc(acc);
    mma_quarter(acc, a_qp + 0 * 64, smb + S_ST_B + buf * 8192 + b_lane);
    mma_quarter(acc, a_qp + 1 * 64, smb + S_ST_B + (buf ^ 1) * 8192 + b_lane);
    __syncthreads();                        // both buffers free
    cpasyncQ(smb, buf, g_pack + PO4 + 4096, tid);
    cpasyncQ(smb, buf ^ 1, g_pack + PO4 + 6144, tid);
    CP_WAIT0(); __syncthreads();
    mma_quarter(acc, a_qp + 2 * 64, smb + S_ST_B + buf * 8192 + b_lane);
    mma_quarter(acc, a_qp + 3 * 64, smb + S_ST_B + (buf ^ 1) * 8192 + b_lane);
    epi_g(out + base, bo, acc, lane, mg, ng);
}

extern "C" void kernel_launch(void* const* d_in, const int* in_sizes, int n_in,
                              void* d_out, int out_size) {
    (void)in_sizes; (void)n_in; (void)out_size;
    const float* query = (const float*)d_in[0];
    const float* key   = (const float*)d_in[1];
    const float* value = (const float*)d_in[2];
    const int*   mask  = (const int*)d_in[3];
    const float* Wq = (const float*)d_in[4];
    const float* bq = (const float*)d_in[5];
    const float* Wk = (const float*)d_in[6];
    const float* bk = (const float*)d_in[7];
    const float* Wv = (const float*)d_in[8];
    const float* bv = (const float*)d_in[9];
    const float* Wo = (const float*)d_in[10];
    const float* bo = (const float*)d_in[11];
    float* out = (float*)d_out;

    cudaFuncSetAttribute(attn_kernel, cudaFuncAttributeMaxDynamicSharedMemorySize, SMEM_BYTES);
    prep_kernel<<<64, 256>>>(Wq, Wk, Wv, Wo);
    attn_kernel<<<4096, 256, SMEM_BYTES>>>(query, key, value, mask, bq, bk, bv, bo, out);
}

// round 17
// speedup vs baseline: 1.2705x; 1.2705x over previous
#include <cuda_runtime.h>
#include <cuda_fp16.h>
#include <cstdint>

// B=8, N=512, T=64, D=128, H=8, DK=16, K=3.
// R17: M=64/CTA, 256 thr = 8 warps, warp tile 32x32, 3 CTA/SM.
// fp16 MMA, fp32 accum. NO smem weight staging: B-fragments read directly
// from g_pack via LDG (L2/L1 cached). 8 barriers total.
// k-tile overwrites dead key input in S_IN; x overwrites dead q tile in QP.

// byte offsets in dynamic smem (per CTA 53824 B)
#define S_IN_B   0          // 68 rows x 272B fp16: value -> query -> key -> k-tile(rows+2)
#define S_QP_B   18496      // 64 x 272B fp16 q tile -> x tile
#define S_VT_B   35904      // 64 x 272B fp16 v tile
#define S_MSK_B  53312      // 64 x ull row masks
#define SMEM_BYTES 53824

// g_pack chunk bases in uint4 units (each 32KB chunk = 2048 uint4)
#define GQ4 0
#define GK4 6144
#define GV4 12288
#define GO4 14336

typedef unsigned long long ull;
__device__ uint32_t g_pack[65536];

// ---------------- PTX helpers ----------------
__device__ __forceinline__ uint32_t smem_u32(const void* p) {
    uint32_t a;
    asm("{ .reg .u64 t; cvta.to.shared.u64 t, %1; cvt.u32.u64 %0, t; }" : "=r"(a) : "l"(p));
    return a;
}
__device__ __forceinline__ uint32_t h2(float lo, float hi) {
    uint32_t r; asm("cvt.rn.f16x2.f32 %0, %1, %2;" : "=r"(r) : "f"(hi), "f"(lo)); return r;
}
__device__ __forceinline__ void ldsm4(uint32_t (&r)[4], uint32_t a) {
    asm volatile("ldmatrix.sync.aligned.m8n8.x4.shared.b16 {%0,%1,%2,%3}, [%4];"
                 : "=r"(r[0]), "=r"(r[1]), "=r"(r[2]), "=r"(r[3]) : "r"(a));
}
__device__ __forceinline__ void ldsm4t(uint32_t (&r)[4], uint32_t a) {
    asm volatile("ldmatrix.sync.aligned.m8n8.x4.trans.shared.b16 {%0,%1,%2,%3}, [%4];"
                 : "=r"(r[0]), "=r"(r[1]), "=r"(r[2]), "=r"(r[3]) : "r"(a));
}
__device__ __forceinline__ void mma16(float (&c)[4], const uint32_t (&a)[4],
                                      uint32_t b0, uint32_t b1) {
    asm volatile(
        "mma.sync.aligned.m16n8k16.row.col.f32.f16.f16.f32 "
        "{%0,%1,%2,%3},{%4,%5,%6,%7},{%8,%9},{%0,%1,%2,%3};"
        : "+f"(c[0]), "+f"(c[1]), "+f"(c[2]), "+f"(c[3])
        : "r"(a[0]), "r"(a[1]), "r"(a[2]), "r"(a[3]), "r"(b0), "r"(b1));
}

// ---------------- prep: pack weights as fp16 B-fragments (unchanged) ------------
__global__ void prep_kernel(const float* __restrict__ Wq, const float* __restrict__ Wk,
                            const float* __restrict__ Wv, const float* __restrict__ Wo) {
    int idx = blockIdx.x * blockDim.x + threadIdx.x;   // 16384
    if (idx >= 16384) return;
    const float* W; int base4, within, j = 0, conv; float sc = 1.0f;
    if (idx < 6144)       { W = Wq; j = idx >> 11; within = idx & 2047; base4 = GQ4 + idx; conv = 1; sc = 0.25f; }
    else if (idx < 12288) { int i2 = idx - 6144; W = Wk; j = i2 >> 11; within = i2 & 2047; base4 = GK4 + i2; conv = 1; }
    else if (idx < 14336) { int i2 = idx - 12288; W = Wv; within = i2; base4 = GV4 + i2; conv = 0; }
    else                  { int i2 = idx - 14336; W = Wo; within = i2; base4 = GO4 + i2; conv = 0; }
    int lane = within & 31, njp = (within >> 5) & 7, ksp = within >> 8;
    int n0 = njp * 16 + (lane >> 2);
    int n1 = n0 + 8;
    int k0 = ksp * 16 + 2 * (lane & 3);
    float w[8];
    if (conv) {
        w[0] = W[(n0 * 128 + k0) * 3 + j];     w[1] = W[(n0 * 128 + k0 + 1) * 3 + j];
        w[2] = W[(n0 * 128 + k0 + 8) * 3 + j]; w[3] = W[(n0 * 128 + k0 + 9) * 3 + j];
        w[4] = W[(n1 * 128 + k0) * 3 + j];     w[5] = W[(n1 * 128 + k0 + 1) * 3 + j];
        w[6] = W[(n1 * 128 + k0 + 8) * 3 + j]; w[7] = W[(n1 * 128 + k0 + 9) * 3 + j];
    } else {
        w[0] = W[n0 * 128 + k0];     w[1] = W[n0 * 128 + k0 + 1];
        w[2] = W[n0 * 128 + k0 + 8]; w[3] = W[n0 * 128 + k0 + 9];
        w[4] = W[n1 * 128 + k0];     w[5] = W[n1 * 128 + k0 + 1];
        w[6] = W[n1 * 128 + k0 + 8]; w[7] = W[n1 * 128 + k0 + 9];
    }
    uint4 o;
    o.x = h2(w[0] * sc, w[1] * sc);
    o.y = h2(w[2] * sc, w[3] * sc);
    o.z = h2(w[4] * sc, w[5] * sc);
    o.w = h2(w[6] * sc, w[7] * sc);
    ((uint4*)g_pack)[base4] = o;
}

// ---------------- building blocks ----------------
__device__ __forceinline__ void load_input(char* smc, const float* __restrict__ g, int tid) {
#pragma unroll
    for (int r = 0; r < 8; r++) {
        int idx = tid + r * 256;
        float4 f = *(const float4*)(g + idx * 4);
        int t = idx >> 5, d = (idx & 31) * 4;
        uint2 v;
        v.x = h2(f.x, f.y);
        v.y = h2(f.z, f.w);
        *(uint2*)(smc + S_IN_B + (t + 2) * 272 + d * 2) = v;
    }
}
// one K=128 chunk (8 k16-steps); B-fragments via LDG from g_pack
__device__ __forceinline__ void mma_chunkG(float (&acc)[2][4][4], uint32_t a0,
                                           const uint4* __restrict__ gB) {
#pragma unroll
    for (int ksp = 0; ksp < 8; ksp++) {
        uint32_t A0[4], A1[4];
        ldsm4(A0, a0 + ksp * 32);
        ldsm4(A1, a0 + 16 * 272 + ksp * 32);
        uint4 B01 = __ldg(gB + ksp * 256);
        uint4 B23 = __ldg(gB + ksp * 256 + 32);
        mma16(acc[0][0], A0, B01.x, B01.y);
        mma16(acc[0][1], A0, B01.z, B01.w);
        mma16(acc[0][2], A0, B23.x, B23.y);
        mma16(acc[0][3], A0, B23.z, B23.w);
        mma16(acc[1][0], A1, B01.x, B01.y);
        mma16(acc[1][1], A1, B01.z, B01.w);
        mma16(acc[1][2], A1, B23.x, B23.y);
        mma16(acc[1][3], A1, B23.z, B23.w);
    }
}
__device__ __forceinline__ void zacc(float (&acc)[2][4][4]) {
#pragma unroll
    for (int s = 0; s < 2; s++)
#pragma unroll
        for (int i = 0; i < 4; i++)
#pragma unroll
            for (int k = 0; k < 4; k++) acc[s][i][k] = 0.f;
}
__device__ __forceinline__ void epi_s(char* smc, int baseoff, const float* __restrict__ bias,
                                      float bscale, float (&acc)[2][4][4],
                                      int lane, int mg, int ng) {
#pragma unroll
    for (int msub = 0; msub < 2; msub++) {
        int r0 = mg * 32 + msub * 16 + (lane >> 2);
#pragma unroll
        for (int nt = 0; nt < 4; nt++) {
            int col = ng * 32 + nt * 8 + (lane & 3) * 2;
            float2 bb = *(const float2*)(bias + col);
            *(uint32_t*)(smc + baseoff + r0 * 272 + col * 2) =
                h2(acc[msub][nt][0] + bb.x * bscale, acc[msub][nt][1] + bb.y * bscale);
            *(uint32_t*)(smc + baseoff + (r0 + 8) * 272 + col * 2) =
                h2(acc[msub][nt][2] + bb.x * bscale, acc[msub][nt][3] + bb.y * bscale);
        }
    }
}
__device__ __forceinline__ void epi_g(float* __restrict__ dst, const float* __restrict__ bias,
                                      float (&acc)[2][4][4], int lane, int mg, int ng) {
#pragma unroll
    for (int msub = 0; msub < 2; msub++) {
        int r0 = mg * 32 + msub * 16 + (lane >> 2);
#pragma unroll
        for (int nt = 0; nt < 4; nt++) {
            int col = ng * 32 + nt * 8 + (lane & 3) * 2;
            float2 bb = *(const float2*)(bias + col);
            *(float2*)(dst + r0 * 128 + col) = make_float2(acc[msub][nt][0] + bb.x, acc[msub][nt][1] + bb.y);
            *(float2*)(dst + (r0 + 8) * 128 + col) = make_float2(acc[msub][nt][2] + bb.x, acc[msub][nt][3] + bb.y);
        }
    }
}

__global__ void __launch_bounds__(256, 3)
attn_kernel(const float* __restrict__ query, const float* __restrict__ key,
            const float* __restrict__ value, const int* __restrict__ mask,
            const float* __restrict__ bq, const float* __restrict__ bk,
            const float* __restrict__ bv, const float* __restrict__ bo,
            float* __restrict__ out)
{
    extern __shared__ char smc[];
    uint32_t smb = smem_u32(smc);
    const int tid = threadIdx.x, lane = tid & 31, wid = tid >> 5;
    const int cta = blockIdx.x, b = cta >> 9;
    const long long base = (long long)cta * 8192;

    const int mg = wid >> 2, ng = wid & 3;
    const int rowbase = mg * 32 + (lane & 15);
    const uint32_t a_in = smb + S_IN_B + (uint32_t)(rowbase * 272 + (lane >> 4) * 16);
    const uint32_t a_qp = smb + S_QP_B + (uint32_t)(rowbase * 272 + (lane >> 4) * 16);
    const uint4* gp4 = (const uint4*)g_pack;
    const int goff = ng * 64 + lane;       // warp/lane offset inside any chunk

    // ---- prologue: pads, masks, value input ----
    if (tid < 136) {
        int rr = tid / 34, off = tid - rr * 34;
        int row = (rr < 2) ? rr : (64 + rr);
        *(ull*)(smc + S_IN_B + row * 272 + off * 8) = 0ull;
    }
    if (tid < 64) {
        ull m = 0;
        const int4* mr = (const int4*)(mask + b * 4096 + tid * 64);
#pragma unroll
        for (int u = 0; u < 16; u++) {
            int4 mm = mr[u];
            ull bits = (ull)(mm.x != 0) | ((ull)(mm.y != 0) << 1) |
                       ((ull)(mm.z != 0) << 2) | ((ull)(mm.w != 0) << 3);
            m |= bits << (u * 4);
        }
        *(ull*)(smc + S_MSK_B + tid * 8) = m;
    }
    load_input(smc, value + base, tid);
    __syncthreads();

    float acc[2][4][4];

    // ---- V GEMM (tap 2) ----
    zacc(acc);
    mma_chunkG(acc, a_in + 2 * 272, gp4 + GV4 + goff);
    __syncthreads();                        // all V-mma reads of S_IN done
    epi_s(smc, S_VT_B, bv, 1.0f, acc, lane, mg, ng);
    load_input(smc, query + base, tid);
    __syncthreads();

    // ---- Q GEMM (taps 0,1,2) ----
    zacc(acc);
    mma_chunkG(acc, a_in + 0 * 272, gp4 + GQ4 + goff);
    mma_chunkG(acc, a_in + 1 * 272, gp4 + GQ4 + 2048 + goff);
    mma_chunkG(acc, a_in + 2 * 272, gp4 + GQ4 + 4096 + goff);
    __syncthreads();                        // all Q-mma reads of S_IN done
    epi_s(smc, S_QP_B, bq, 0.25f, acc, lane, mg, ng);
    load_input(smc, key + base, tid);
    __syncthreads();

    // ---- K GEMM (taps 1,2,3) ----
    zacc(acc);
    mma_chunkG(acc, a_in + 1 * 272, gp4 + GK4 + goff);
    mma_chunkG(acc, a_in + 2 * 272, gp4 + GK4 + 2048 + goff);
    mma_chunkG(acc, a_in + 3 * 272, gp4 + GK4 + 4096 + goff);
    __syncthreads();                        // all K-mma reads of S_IN done
    // k-tile overwrites dead key input (rows+2)
    epi_s(smc, S_IN_B + 544, bk, 1.0f, acc, lane, mg, ng);
    __syncthreads();                        // k/q/v tiles visible

    // ---- attention: warp = head wid; rh x mt serial; x -> QP rows ----
    {
        const int h = wid;
        const int r = lane >> 2, c = lane & 3;
        const uint32_t kt_thr = smb + S_IN_B + 544u
            + (uint32_t)((((lane >> 4) << 3) + (lane & 7)) * 272
                         + h * 32 + ((lane >> 3) & 1) * 16);
        const uint32_t vt_thr = smb + S_VT_B
            + (uint32_t)(((((lane >> 3) & 1) << 3) + (lane & 7)) * 272
                         + h * 32 + (lane >> 4) * 16);
#pragma unroll 1
        for (int rh = 0; rh < 2; rh++) {
            const int mh = rh * 32;
#pragma unroll 1
            for (int mt = 0; mt < 2; mt++) {
                float pa[8][4];
#pragma unroll
                for (int nt = 0; nt < 8; nt++)
#pragma unroll
                    for (int i = 0; i < 4; i++) pa[nt][i] = 0.f;

                uint32_t A[4];
                ldsm4(A, smb + S_QP_B
                         + (uint32_t)((mh + mt * 16 + (lane & 15)) * 272
                                      + h * 32 + (lane >> 4) * 16));
#pragma unroll
                for (int ntp = 0; ntp < 4; ntp++) {
                    uint32_t Bf[4];
                    ldsm4(Bf, kt_thr + (uint32_t)(ntp * 16 * 272));
                    mma16(pa[2 * ntp], A, Bf[0], Bf[1]);
                    mma16(pa[2 * ntp + 1], A, Bf[2], Bf[3]);
                }

                ull mA = *(const ull*)(smc + S_MSK_B + (mh + mt * 16 + r) * 8);
                ull mB = *(const ull*)(smc + S_MSK_B + (mh + mt * 16 + r + 8) * 8);
                float mxA = -3.0e38f, mxB = -3.0e38f;
#pragma unroll
                for (int nt = 0; nt < 8; nt++) {
                    int c0 = nt * 8 + 2 * c, c1 = c0 + 1;
                    float v;
                    v = ((mA >> c0) & 1) ? pa[nt][0] : -1.0e9f; pa[nt][0] = v; mxA = fmaxf(mxA, v);
                    v = ((mA >> c1) & 1) ? pa[nt][1] : -1.0e9f; pa[nt][1] = v; mxA = fmaxf(mxA, v);
                    v = ((mB >> c0) & 1) ? pa[nt][2] : -1.0e9f; pa[nt][2] = v; mxB = fmaxf(mxB, v);
                    v = ((mB >> c1) & 1) ? pa[nt][3] : -1.0e9f; pa[nt][3] = v; mxB = fmaxf(mxB, v);
                }
                mxA = fmaxf(mxA, __shfl_xor_sync(0xffffffffu, mxA, 1));
                mxA = fmaxf(mxA, __shfl_xor_sync(0xffffffffu, mxA, 2));
                mxB = fmaxf(mxB, __shfl_xor_sync(0xffffffffu, mxB, 1));
                mxB = fmaxf(mxB, __shfl_xor_sync(0xffffffffu, mxB, 2));
                float sA = 0.f, sB = 0.f;
#pragma unroll
                for (int nt = 0; nt < 8; nt++) {
                    float e;
                    e = __expf(pa[nt][0] - mxA); pa[nt][0] = e; sA += e;
                    e = __expf(pa[nt][1] - mxA); pa[nt][1] = e; sA += e;
                    e = __expf(pa[nt][2] - mxB); pa[nt][2] = e; sB += e;
                    e = __expf(pa[nt][3] - mxB); pa[nt][3] = e; sB += e;
                }
                sA += __shfl_xor_sync(0xffffffffu, sA, 1);
                sA += __shfl_xor_sync(0xffffffffu, sA, 2);
                sB += __shfl_xor_sync(0xffffffffu, sB, 1);
                sB += __shfl_xor_sync(0xffffffffu, sB, 2);
                float iA = 1.0f / sA, iB = 1.0f / sB;

                float xacc[2][4];
#pragma unroll
                for (int n2 = 0; n2 < 2; n2++)
#pragma unroll
                    for (int i = 0; i < 4; i++) xacc[n2][i] = 0.f;
#pragma unroll
                for (int kp = 0; kp < 4; kp++) {
                    uint32_t Vf[4];
                    ldsm4t(Vf, vt_thr + (uint32_t)(kp * 16 * 272));
                    uint32_t Ax[4];
                    Ax[0] = h2(pa[2 * kp][0], pa[2 * kp][1]);
                    Ax[1] = h2(pa[2 * kp][2], pa[2 * kp][3]);
                    Ax[2] = h2(pa[2 * kp + 1][0], pa[2 * kp + 1][1]);
                    Ax[3] = h2(pa[2 * kp + 1][2], pa[2 * kp + 1][3]);
                    mma16(xacc[0], Ax, Vf[0], Vf[1]);
                    mma16(xacc[1], Ax, Vf[2], Vf[3]);
                }

                int rA = mh + mt * 16 + r, rB = rA + 8;
#pragma unroll
                for (int n2 = 0; n2 < 2; n2++) {
                    int col = h * 16 + n2 * 8 + 2 * c;
                    *(uint32_t*)(smc + S_QP_B + rA * 272 + col * 2) =
                        h2(xacc[n2][0] * iA, xacc[n2][1] * iA);
                    *(uint32_t*)(smc + S_QP_B + rB * 272 + col * 2) =
                        h2(xacc[n2][2] * iB, xacc[n2][3] * iB);
                }
            }
        }
    }
    __syncthreads();                        // x tile visible

    // ---- O-projection from x tile (QP rows 0-63) ----
    zacc(acc);
    mma_chunkG(acc, a_qp, gp4 + GO4 + goff);
    epi_g(out + base, bo, acc, lane, mg, ng);
}

extern "C" void kernel_launch(void* const* d_in, const int* in_sizes, int n_in,
                              void* d_out, int out_size) {
    (void)in_sizes; (void)n_in; (void)out_size;
    const float* query = (const float*)d_in[0];
    const float* key   = (const float*)d_in[1];
    const float* value = (const float*)d_in[2];
    const int*   mask  = (const int*)d_in[3];
    const float* Wq = (const float*)d_in[4];
    const float* bq = (const float*)d_in[5];
    const float* Wk = (const float*)d_in[6];
    const float* bk = (const float*)d_in[7];
    const float* Wv = (const float*)d_in[8];
    const float* bv = (const float*)d_in[9];
    const float* Wo = (const float*)d_in[10];
    const float* bo = (const float*)d_in[11];
    float* out = (float*)d_out;

    cudaFuncSetAttribute(attn_kernel, cudaFuncAttributeMaxDynamicSharedMemorySize, SMEM_BYTES);
    prep_kernel<<<64, 256>>>(Wq, Wk, Wv, Wo);
    attn_kernel<<<4096, 256, SMEM_BYTES>>>(query, key, value, mask, bq, bk, bv, bo, out);
}